// round 2
// baseline (speedup 1.0000x reference)
#include <cuda_runtime.h>

#define BS 64
#define NUM_ACTION 125
#define NUM_NOUN 352
#define NUM_CLS (NUM_ACTION + NUM_NOUN)   // 477
#define DD 5
#define HW 1024                            // 32*32
#define SS (HW * DD)                       // 5120
#define CH_TOTAL ((64 + NUM_ACTION + NUM_NOUN) * DD)  // 2705
#define CONF_BASE (63 * DD)                // channel 63 -> pred channels 315..319
#define NTH 256
#define NWARP (NTH / 32)

__device__ float g_losses[BS * 2];
__device__ unsigned int g_done = 0;

__device__ __forceinline__ void amax_upd(float v, int s, float& bv, int& bs_) {
    if (v > bv || (v == bv && s < bs_)) { bv = v; bs_ = s; }
}

__global__ void __launch_bounds__(NTH) fused_kernel(
    const float* __restrict__ pred,
    const int* __restrict__ action_gt,
    const int* __restrict__ noun_gt,
    float* __restrict__ out)
{
    const int b = blockIdx.x;
    const int t = threadIdx.x;
    const int lane = t & 31;
    const int wid  = t >> 5;
    const float* base = pred + (size_t)b * CH_TOTAL * HW;
    const float4* conf4 = (const float4*)(base + (size_t)CONF_BASE * HW); // 1280 float4

    // ---- Phase 1: argmax over s = hw*5 + d (first-max tie-break) ----
    float bv = -__int_as_float(0x7f800000);
    int   bsi = 0x7fffffff;
    #pragma unroll
    for (int k = 0; k < 5; k++) {
        int i4 = t + k * NTH;               // < 1280
        float4 v = conf4[i4];
        int j = i4 * 4;
        int d = j >> 10, hw = j & 1023;
        // 4 consecutive elements share d (1024 % 4 == 0 so no d-boundary inside a float4)
        amax_upd(v.x, (hw + 0) * DD + d, bv, bsi);
        amax_upd(v.y, (hw + 1) * DD + d, bv, bsi);
        amax_upd(v.z, (hw + 2) * DD + d, bv, bsi);
        amax_upd(v.w, (hw + 3) * DD + d, bv, bsi);
    }
    // warp reduce (val, idx)
    #pragma unroll
    for (int off = 16; off > 0; off >>= 1) {
        float ov = __shfl_down_sync(0xffffffff, bv, off);
        int   os = __shfl_down_sync(0xffffffff, bsi, off);
        amax_upd(ov, os, bv, bsi);
    }
    __shared__ float wval[NWARP];
    __shared__ int   widx[NWARP];
    if (lane == 0) { wval[wid] = bv; widx[wid] = bsi; }
    __syncthreads();
    __shared__ int s_top;
    if (t == 0) {
        float fv = wval[0]; int fs = widx[0];
        #pragma unroll
        for (int w = 1; w < NWARP; w++) amax_upd(wval[w], widx[w], fv, fs);
        s_top = fs;
    }
    __syncthreads();
    const int top = s_top;
    const int d   = top % DD;
    const int hw  = top / DD;

    // ---- Phase 2: gather 477 chosen logits into smem ----
    __shared__ float ch[NUM_CLS];
    for (int c = t; c < NUM_CLS; c += NTH)
        ch[c] = base[(size_t)((64 + c) * DD + d) * HW + hw];
    __syncthreads();

    // ---- Phase 3: two logsumexps (warp-level) ----
    __shared__ float wred[NWARP];
    float lse_a, lse_n;

    // action
    {
        float m = -__int_as_float(0x7f800000);
        for (int c = t; c < NUM_ACTION; c += NTH) m = fmaxf(m, ch[c]);
        #pragma unroll
        for (int off = 16; off > 0; off >>= 1)
            m = fmaxf(m, __shfl_down_sync(0xffffffff, m, off));
        if (lane == 0) wred[wid] = m;
        __syncthreads();
        if (t == 0) {
            float mm = wred[0];
            #pragma unroll
            for (int w = 1; w < NWARP; w++) mm = fmaxf(mm, wred[w]);
            wred[0] = mm;
        }
        __syncthreads();
        const float amax = wred[0];
        __syncthreads();
        float acc = 0.f;
        for (int c = t; c < NUM_ACTION; c += NTH) acc += expf(ch[c] - amax);
        #pragma unroll
        for (int off = 16; off > 0; off >>= 1)
            acc += __shfl_down_sync(0xffffffff, acc, off);
        if (lane == 0) wred[wid] = acc;
        __syncthreads();
        if (t == 0) {
            float ss = wred[0];
            #pragma unroll
            for (int w = 1; w < NWARP; w++) ss += wred[w];
            wred[0] = amax + logf(ss);
        }
        __syncthreads();
        lse_a = wred[0];
        __syncthreads();
    }
    // noun
    {
        float m = -__int_as_float(0x7f800000);
        for (int c = t; c < NUM_NOUN; c += NTH) m = fmaxf(m, ch[NUM_ACTION + c]);
        #pragma unroll
        for (int off = 16; off > 0; off >>= 1)
            m = fmaxf(m, __shfl_down_sync(0xffffffff, m, off));
        if (lane == 0) wred[wid] = m;
        __syncthreads();
        if (t == 0) {
            float mm = wred[0];
            #pragma unroll
            for (int w = 1; w < NWARP; w++) mm = fmaxf(mm, wred[w]);
            wred[0] = mm;
        }
        __syncthreads();
        const float nmax = wred[0];
        __syncthreads();
        float acc = 0.f;
        for (int c = t; c < NUM_NOUN; c += NTH) acc += expf(ch[NUM_ACTION + c] - nmax);
        #pragma unroll
        for (int off = 16; off > 0; off >>= 1)
            acc += __shfl_down_sync(0xffffffff, acc, off);
        if (lane == 0) wred[wid] = acc;
        __syncthreads();
        if (t == 0) {
            float ss = wred[0];
            #pragma unroll
            for (int w = 1; w < NWARP; w++) ss += wred[w];
            wred[0] = nmax + logf(ss);
        }
        __syncthreads();
        lse_n = wred[0];
    }

    if (t == 0) {
        g_losses[b * 2 + 0] = lse_a - ch[action_gt[b]];
        g_losses[b * 2 + 1] = lse_n - ch[NUM_ACTION + noun_gt[b]];
        __threadfence();
    }
    __syncthreads();

    // ---- last-CTA finalize ----
    __shared__ unsigned int is_last;
    if (t == 0) is_last = (atomicAdd(&g_done, 1u) == BS - 1) ? 1u : 0u;
    __syncthreads();
    if (is_last) {
        __threadfence();
        __shared__ float sa[BS], sn[BS];
        if (t < BS) {
            sa[t] = ((volatile float*)g_losses)[t * 2 + 0];
            sn[t] = ((volatile float*)g_losses)[t * 2 + 1];
        }
        __syncthreads();
        #pragma unroll
        for (int off = BS / 2; off > 0; off >>= 1) {
            if (t < off) { sa[t] += sa[t + off]; sn[t] += sn[t + off]; }
            __syncthreads();
        }
        if (t == 0) {
            const float la = sa[0] * 0.5f;
            const float ln = sn[0] * 0.5f;
            out[0] = la + ln;
            out[1] = la;
            out[2] = ln;
            g_done = 0;   // reset for next graph replay
        }
    }
}

extern "C" void kernel_launch(void* const* d_in, const int* in_sizes, int n_in,
                              void* d_out, int out_size)
{
    const float* pred = (const float*)d_in[0];
    const int*   ag   = (const int*)d_in[1];
    const int*   ng   = (const int*)d_in[2];
    float* out = (float*)d_out;

    fused_kernel<<<BS, NTH>>>(pred, ag, ng, out);
}

// round 3
// speedup vs baseline: 1.2601x; 1.2601x over previous
#include <cuda_runtime.h>

#define BS 64
#define NUM_ACTION 125
#define NUM_NOUN 352
#define NUM_CLS (NUM_ACTION + NUM_NOUN)   // 477
#define DD 5
#define HW 1024                            // 32*32
#define SS (HW * DD)                       // 5120
#define CH_TOTAL ((64 + NUM_ACTION + NUM_NOUN) * DD)  // 2705
#define CONF_BASE (63 * DD)                // channel 63 -> pred channels 315..319
#define NTH 256
#define NWARP (NTH / 32)

__device__ float g_losses[BS * 2];
__device__ unsigned int g_done = 0;

__device__ __forceinline__ void amax_upd(float v, int s, float& bv, int& bs_) {
    if (v > bv || (v == bv && s < bs_)) { bv = v; bs_ = s; }
}

__global__ void __launch_bounds__(NTH) fused_kernel(
    const float* __restrict__ pred,
    const int* __restrict__ action_gt,
    const int* __restrict__ noun_gt,
    float* __restrict__ out)
{
    const int b = blockIdx.x;
    const int t = threadIdx.x;
    const int lane = t & 31;
    const int wid  = t >> 5;
    const float* base = pred + (size_t)b * CH_TOTAL * HW;
    const float4* conf4 = (const float4*)(base + (size_t)CONF_BASE * HW); // 1280 float4

    // ---- Phase 1: argmax over s = hw*5 + d (first-max tie-break) ----
    float bv = -__int_as_float(0x7f800000);
    int   bsi = 0x7fffffff;
    #pragma unroll
    for (int k = 0; k < 5; k++) {
        int i4 = t + k * NTH;               // < 1280
        float4 v = conf4[i4];
        int j = i4 * 4;
        int d = j >> 10, hw = j & 1023;
        // 4 consecutive elements share d (1024 % 4 == 0 so no d-boundary inside a float4)
        amax_upd(v.x, (hw + 0) * DD + d, bv, bsi);
        amax_upd(v.y, (hw + 1) * DD + d, bv, bsi);
        amax_upd(v.z, (hw + 2) * DD + d, bv, bsi);
        amax_upd(v.w, (hw + 3) * DD + d, bv, bsi);
    }
    // warp reduce (val, idx)
    #pragma unroll
    for (int off = 16; off > 0; off >>= 1) {
        float ov = __shfl_down_sync(0xffffffff, bv, off);
        int   os = __shfl_down_sync(0xffffffff, bsi, off);
        amax_upd(ov, os, bv, bsi);
    }
    __shared__ float wval[NWARP];
    __shared__ int   widx[NWARP];
    if (lane == 0) { wval[wid] = bv; widx[wid] = bsi; }
    __syncthreads();
    __shared__ int s_top;
    if (t == 0) {
        float fv = wval[0]; int fs = widx[0];
        #pragma unroll
        for (int w = 1; w < NWARP; w++) amax_upd(wval[w], widx[w], fv, fs);
        s_top = fs;
    }
    __syncthreads();
    const int top = s_top;
    const int d   = top % DD;
    const int hw  = top / DD;

    // ---- Phase 2: gather 477 chosen logits into smem ----
    __shared__ float ch[NUM_CLS];
    for (int c = t; c < NUM_CLS; c += NTH)
        ch[c] = base[(size_t)((64 + c) * DD + d) * HW + hw];
    __syncthreads();

    // ---- Phase 3: two logsumexps (warp-level) ----
    __shared__ float wred[NWARP];
    float lse_a, lse_n;

    // action
    {
        float m = -__int_as_float(0x7f800000);
        for (int c = t; c < NUM_ACTION; c += NTH) m = fmaxf(m, ch[c]);
        #pragma unroll
        for (int off = 16; off > 0; off >>= 1)
            m = fmaxf(m, __shfl_down_sync(0xffffffff, m, off));
        if (lane == 0) wred[wid] = m;
        __syncthreads();
        if (t == 0) {
            float mm = wred[0];
            #pragma unroll
            for (int w = 1; w < NWARP; w++) mm = fmaxf(mm, wred[w]);
            wred[0] = mm;
        }
        __syncthreads();
        const float amax = wred[0];
        __syncthreads();
        float acc = 0.f;
        for (int c = t; c < NUM_ACTION; c += NTH) acc += expf(ch[c] - amax);
        #pragma unroll
        for (int off = 16; off > 0; off >>= 1)
            acc += __shfl_down_sync(0xffffffff, acc, off);
        if (lane == 0) wred[wid] = acc;
        __syncthreads();
        if (t == 0) {
            float ss = wred[0];
            #pragma unroll
            for (int w = 1; w < NWARP; w++) ss += wred[w];
            wred[0] = amax + logf(ss);
        }
        __syncthreads();
        lse_a = wred[0];
        __syncthreads();
    }
    // noun
    {
        float m = -__int_as_float(0x7f800000);
        for (int c = t; c < NUM_NOUN; c += NTH) m = fmaxf(m, ch[NUM_ACTION + c]);
        #pragma unroll
        for (int off = 16; off > 0; off >>= 1)
            m = fmaxf(m, __shfl_down_sync(0xffffffff, m, off));
        if (lane == 0) wred[wid] = m;
        __syncthreads();
        if (t == 0) {
            float mm = wred[0];
            #pragma unroll
            for (int w = 1; w < NWARP; w++) mm = fmaxf(mm, wred[w]);
            wred[0] = mm;
        }
        __syncthreads();
        const float nmax = wred[0];
        __syncthreads();
        float acc = 0.f;
        for (int c = t; c < NUM_NOUN; c += NTH) acc += expf(ch[NUM_ACTION + c] - nmax);
        #pragma unroll
        for (int off = 16; off > 0; off >>= 1)
            acc += __shfl_down_sync(0xffffffff, acc, off);
        if (lane == 0) wred[wid] = acc;
        __syncthreads();
        if (t == 0) {
            float ss = wred[0];
            #pragma unroll
            for (int w = 1; w < NWARP; w++) ss += wred[w];
            wred[0] = nmax + logf(ss);
        }
        __syncthreads();
        lse_n = wred[0];
    }

    if (t == 0) {
        g_losses[b * 2 + 0] = lse_a - ch[action_gt[b]];
        g_losses[b * 2 + 1] = lse_n - ch[NUM_ACTION + noun_gt[b]];
        __threadfence();
    }
    __syncthreads();

    // ---- last-CTA finalize ----
    __shared__ unsigned int is_last;
    if (t == 0) is_last = (atomicAdd(&g_done, 1u) == BS - 1) ? 1u : 0u;
    __syncthreads();
    if (is_last) {
        __threadfence();
        __shared__ float sa[BS], sn[BS];
        if (t < BS) {
            sa[t] = ((volatile float*)g_losses)[t * 2 + 0];
            sn[t] = ((volatile float*)g_losses)[t * 2 + 1];
        }
        __syncthreads();
        #pragma unroll
        for (int off = BS / 2; off > 0; off >>= 1) {
            if (t < off) { sa[t] += sa[t + off]; sn[t] += sn[t + off]; }
            __syncthreads();
        }
        if (t == 0) {
            const float la = sa[0] * 0.5f;
            const float ln = sn[0] * 0.5f;
            out[0] = la + ln;
            out[1] = la;
            out[2] = ln;
            g_done = 0;   // reset for next graph replay
        }
    }
}

extern "C" void kernel_launch(void* const* d_in, const int* in_sizes, int n_in,
                              void* d_out, int out_size)
{
    const float* pred = (const float*)d_in[0];
    const int*   ag   = (const int*)d_in[1];
    const int*   ng   = (const int*)d_in[2];
    float* out = (float*)d_out;

    fused_kernel<<<BS, NTH>>>(pred, ag, ng, out);
}